// round 1
// baseline (speedup 1.0000x reference)
#include <cuda_runtime.h>
#include <cstdint>

// WeightedBCELoss: out[b,s] = (labels[b,s]==0) ? -log(1-pred) : -weight[b]*log(pred)
// Shapes: pred [4096,8192] f32, labels [4096,8192] i32, weight [4096] f32.
// Pure HBM-streaming kernel: ~402 MiB traffic, target ~55-65 us.

#define BATCH 4096
#define SENT  8192

__global__ __launch_bounds__(256, 8)
void wbce_kernel(const float4* __restrict__ pred,
                 const int4*   __restrict__ labels,
                 const float*  __restrict__ weight,
                 float4*       __restrict__ out)
{
    // grid: (SENT/4/256 = 8, BATCH); each thread does one float4.
    const int row = blockIdx.y;
    const int v   = blockIdx.x * blockDim.x + threadIdx.x;      // float4 index in row
    const long idx = (long)row * (SENT / 4) + v;

    const float w = __ldg(&weight[row]);

    float4 p = pred[idx];
    int4   l = labels[idx];

    float4 r;
    {
        float arg   = (l.x == 0) ? (1.0f - p.x) : p.x;
        float scale = (l.x == 0) ? 1.0f : w;
        r.x = -scale * __logf(arg);
    }
    {
        float arg   = (l.y == 0) ? (1.0f - p.y) : p.y;
        float scale = (l.y == 0) ? 1.0f : w;
        r.y = -scale * __logf(arg);
    }
    {
        float arg   = (l.z == 0) ? (1.0f - p.z) : p.z;
        float scale = (l.z == 0) ? 1.0f : w;
        r.z = -scale * __logf(arg);
    }
    {
        float arg   = (l.w == 0) ? (1.0f - p.w) : p.w;
        float scale = (l.w == 0) ? 1.0f : w;
        r.w = -scale * __logf(arg);
    }

    out[idx] = r;
}

extern "C" void kernel_launch(void* const* d_in, const int* in_sizes, int n_in,
                              void* d_out, int out_size)
{
    const float4* pred   = (const float4*)d_in[0];
    const int4*   labels = (const int4*)d_in[1];
    const float*  weight = (const float*)d_in[2];
    float4*       out    = (float4*)d_out;

    dim3 block(256);
    dim3 grid(SENT / 4 / 256, BATCH);   // (8, 4096)
    wbce_kernel<<<grid, block>>>(pred, labels, weight, out);
}